// round 17
// baseline (speedup 1.0000x reference)
// R17 = R16 resubmission (container-level infra failure, no harness evidence;
// identical re-run per R10/R15 precedent).
// Delta vs R15 (passing, 887 us): MLP GEMM loops restructured for latency
// hiding — register prefetch at loop top, 16-row W1 tiles (8 iters), 32-row
// W2 tiles (16 iters), one barrier/iter, W2 tile-0 staged during LN.
#include <cuda_runtime.h>
#include <mma.h>

using namespace nvcuda;

#define NN 100000
#define EE 1600000
#define FF 128

#define AS 136    // feat tile / W2 k-tile / conv tile stride
#define HS 520    // W1 k-tile / h1 stride
#define MLP_SMEM_FLOATS (32 * HS + 2 * 32 * AS)     // 16640 + 8704 = 25344
#define MLP_SMEM_BYTES  (MLP_SMEM_FLOATS * 4)       // 101376

// ---- scratch (device globals; ~112 MB) ----
__device__ int   g_deg_out[NN];
__device__ int   g_deg_in[NN];
__device__ float g_ns[NN];
__device__ float g_nd[NN];
__device__ float g_y[NN * FF];
__device__ float g_agg[NN * FF];
__device__ float g_w1r[128 * 512];
__device__ float g_w2r[512 * 128];
__device__ float g_wc0r[128 * 128];
__device__ float g_wc1r[128 * 128];
__device__ float g_E[24 * 512];
__device__ int   g_ptr[NN];
__device__ int   g_cnt[NN];
__device__ int   g_csr[EE];
__device__ int   g_total;

__device__ __forceinline__ float tf32r(float v) {
    unsigned int r;
    asm("cvt.rna.tf32.f32 %0, %1;" : "=r"(r) : "f"(v));
    return __uint_as_float(r);
}

// ------------------------------------------------------------------
__global__ void zero_deg_kernel() {
    int i = blockIdx.x * blockDim.x + threadIdx.x;
    if (i < NN) { g_deg_out[i] = 0; g_deg_in[i] = 0; }
    if (i == 0) g_total = 0;
}

__global__ void deg_round_kernel(const int* __restrict__ src, const int* __restrict__ dst,
                                 const float* __restrict__ W1, const float* __restrict__ W2,
                                 const float* __restrict__ Wc0, const float* __restrict__ Wc1)
{
    int e = blockIdx.x * blockDim.x + threadIdx.x;
    if (e < EE) {
        atomicAdd(&g_deg_out[src[e]], 1);
        atomicAdd(&g_deg_in[dst[e]], 1);
    }
    if (e < 163840) {
        int i = e;
        if (i < 65536)       g_w1r[i] = tf32r(W1[i]);
        else if (i < 131072) g_w2r[i - 65536] = tf32r(W2[i - 65536]);
        else if (i < 147456) g_wc0r[i - 131072] = tf32r(Wc0[i - 131072]);
        else                 g_wc1r[i - 147456] = tf32r(Wc1[i - 147456]);
    }
}

__global__ void norm_prep_kernel(const float* __restrict__ emb,
                                 const float* __restrict__ W1,
                                 const float* __restrict__ b1)
{
    int i = blockIdx.x * blockDim.x + threadIdx.x;
    int lane = threadIdx.x & 31;
    bool valid = i < NN;

    int dd = 0;
    if (valid) {
        int dn = g_deg_out[i];
        dd = g_deg_in[i];
        g_ns[i] = dn > 0 ? rsqrtf((float)dn) : 0.0f;
        g_nd[i] = dd > 0 ? rsqrtf((float)dd) : 0.0f;
    }

    int incl = dd;
    #pragma unroll
    for (int off = 1; off < 32; off <<= 1) {
        int v = __shfl_up_sync(0xffffffffu, incl, off);
        if (lane >= off) incl += v;
    }
    int wtot = __shfl_sync(0xffffffffu, incl, 31);
    int base = 0;
    if (lane == 31) base = atomicAdd(&g_total, wtot);
    base = __shfl_sync(0xffffffffu, base, 31);

    if (valid) {
        int p = base + incl - dd;
        g_ptr[i] = p;
        g_cnt[i] = p;
    }

    if (i < 24 * 512) {
        int c = i >> 9, j = i & 511;
        float s = __ldg(&b1[j]);
        #pragma unroll 8
        for (int k = 0; k < 128; k++)
            s += emb[c * 128 + k] * W1[(128 + k) * 512 + j];
        g_E[i] = s;
    }
}

__device__ __forceinline__ float warp_sum(float v) {
    #pragma unroll
    for (int o = 16; o > 0; o >>= 1) v += __shfl_xor_sync(0xffffffffu, v, o);
    return v;
}

__global__ void fill_kernel(const int* __restrict__ src, const int* __restrict__ dst)
{
    int e = blockIdx.x * blockDim.x + threadIdx.x;
    if (e < EE) {
        int slot = atomicAdd(&g_cnt[dst[e]], 1);
        g_csr[slot] = src[e];
    }
}

__global__ void __launch_bounds__(256) gather_kernel()
{
    int n = (blockIdx.x * 256 + threadIdx.x) >> 5;
    int lane = threadIdx.x & 31;
    if (n >= NN) return;
    int p = g_ptr[n];
    int pe = p + g_deg_in[n];

    float4 acc = make_float4(0.f, 0.f, 0.f, 0.f);
    int j = p;
    for (; j + 4 <= pe; j += 4) {
        int s0 = __ldg(&g_csr[j]);
        int s1 = __ldg(&g_csr[j + 1]);
        int s2 = __ldg(&g_csr[j + 2]);
        int s3 = __ldg(&g_csr[j + 3]);
        float4 v0 = ((const float4*)(g_y + (size_t)s0 * 128))[lane];
        float4 v1 = ((const float4*)(g_y + (size_t)s1 * 128))[lane];
        float4 v2 = ((const float4*)(g_y + (size_t)s2 * 128))[lane];
        float4 v3 = ((const float4*)(g_y + (size_t)s3 * 128))[lane];
        acc.x += v0.x + v1.x + v2.x + v3.x;
        acc.y += v0.y + v1.y + v2.y + v3.y;
        acc.z += v0.z + v1.z + v2.z + v3.z;
        acc.w += v0.w + v1.w + v2.w + v3.w;
    }
    for (; j < pe; j++) {
        int s = __ldg(&g_csr[j]);
        float4 v = ((const float4*)(g_y + (size_t)s * 128))[lane];
        acc.x += v.x; acc.y += v.y; acc.z += v.z; acc.w += v.w;
    }
    ((float4*)(g_agg + (size_t)n * 128))[lane] = acc;
}

// ------------------------------------------------------------------
// Fused MLP, 32 rows/block, 256 threads (8 warps, 2m x 4n).
// GEMM1: K=128 in 8 double-buffered 16-row W1 tiles, prefetch at loop top.
// GEMM2: K=512 in 16 double-buffered 32-row W2 tiles, prefetch at loop top;
//        tile 0 staged during LN. One barrier per iteration throughout.
__global__ void __launch_bounds__(256, 2) mlp_kernel(
    const float* __restrict__ feat, const int* __restrict__ labels,
    const float* __restrict__ g1, const float* __restrict__ be1,
    const float* __restrict__ b2)
{
    extern __shared__ float sm[];
    float* sH = sm;               // 16640 floats: W1 dbuf 2x16xHS, then h1 32xHS
    float* sA = sm + 32 * HS;     // 8704 floats: feat 32xAS, then W2 dbuf 2x32xAS,
                                  // then epilogue 32x128

    const int tid = threadIdx.x;
    const int w   = tid >> 5;
    const int cl  = tid & 31;
    const int wm  = w & 1;
    const int wn  = w >> 1;
    const int n0g = blockIdx.x * 32;
    const int row0 = wm * 16;

    // ---- load feat tile [32][128] (tf32) + stage W1 k-tile 0 (16x512) ----
    #pragma unroll
    for (int q = 0; q < 4; q++) {
        int i = tid + q * 256;
        int r = i >> 5, c4 = i & 31;
        float4 v = ((const float4*)feat)[(size_t)(n0g + r) * 32 + c4];
        v.x = tf32r(v.x); v.y = tf32r(v.y); v.z = tf32r(v.z); v.w = tf32r(v.w);
        ((float4*)(sA + r * AS))[c4] = v;
    }
    {
        const float4* src = (const float4*)g_w1r;
        #pragma unroll
        for (int q = 0; q < 8; q++) {
            int i = tid + q * 256;        // 2048 float4 = 16x512
            int r = i >> 7, c4 = i & 127;
            ((float4*)(sH + r * HS))[c4] = src[i];
        }
    }
    __syncthreads();

    // ---- GEMM1: [32,128] @ [128,512] ----
    wmma::fragment<wmma::accumulator, 16, 16, 8, float> c1[8];
    #pragma unroll
    for (int j = 0; j < 8; j++) wmma::fill_fragment(c1[j], 0.0f);

    const int n0 = wn * 128;
    for (int kt = 0; kt < 8; kt++) {
        float4 pre[8];
        if (kt < 7) {
            const float4* src = (const float4*)g_w1r + (kt + 1) * 2048;
            #pragma unroll
            for (int q = 0; q < 8; q++) pre[q] = src[tid + q * 256];
        }
        const float* cur = sH + (kt & 1) * (16 * HS);

        #pragma unroll
        for (int ks = 0; ks < 2; ks++) {
            wmma::fragment<wmma::matrix_a, 16, 16, 8, wmma::precision::tf32, wmma::row_major> a;
            wmma::load_matrix_sync(a, sA + row0 * AS + kt * 16 + ks * 8, AS);
            #pragma unroll
            for (int j = 0; j < 8; j++) {
                wmma::fragment<wmma::matrix_b, 16, 16, 8, wmma::precision::tf32, wmma::row_major> b;
                wmma::load_matrix_sync(b, cur + (ks * 8) * HS + n0 + j * 16, HS);
                wmma::mma_sync(c1[j], a, b, c1[j]);
            }
        }

        if (kt < 7) {
            float* nxt = sH + ((kt + 1) & 1) * (16 * HS);
            #pragma unroll
            for (int q = 0; q < 8; q++) {
                int i = tid + q * 256;
                int r = i >> 7, c4 = i & 127;
                ((float4*)(nxt + r * HS))[c4] = pre[q];
            }
        }
        __syncthreads();
    }

    // ---- h_raw -> sH (h1 layout, stride HS) ----
    #pragma unroll
    for (int j = 0; j < 8; j++)
        wmma::store_matrix_sync(sH + row0 * HS + n0 + j * 16, c1[j], HS, wmma::mem_row_major);
    __syncthreads();

    // ---- stage W2 tile 0 (32x128) into sA buf0 (feat dead), overlapped with LN ----
    {
        const float4* src = (const float4*)g_w2r;
        #pragma unroll
        for (int q = 0; q < 4; q++) {
            int i = tid + q * 256;        // 1024 float4 = 32x128
            int r = i >> 5, c4 = i & 31;
            ((float4*)(sA + r * AS))[c4] = src[i];
        }
    }

    // ---- + E[label], LayerNorm(512), *g1+be1, relu, tf32 round (in place) ----
    #pragma unroll
    for (int i = 0; i < 4; i++) {
        int r = w * 4 + i;
        const float* Ep = g_E + __ldg(&labels[n0g + r]) * 512;
        float vals[16];
        float s = 0.f;
        #pragma unroll
        for (int jj = 0; jj < 16; jj++) {
            int col = cl + 32 * jj;
            vals[jj] = sH[r * HS + col] + __ldg(&Ep[col]);
            s += vals[jj];
        }
        float mu = warp_sum(s) * (1.0f / 512.0f);
        float v = 0.f;
        #pragma unroll
        for (int jj = 0; jj < 16; jj++) {
            float d = vals[jj] - mu;
            v += d * d;
        }
        float rstd = rsqrtf(warp_sum(v) * (1.0f / 512.0f) + 1e-5f);
        #pragma unroll
        for (int jj = 0; jj < 16; jj++) {
            int col = cl + 32 * jj;
            float x = (vals[jj] - mu) * rstd * __ldg(&g1[col]) + __ldg(&be1[col]);
            sH[r * HS + col] = tf32r(fmaxf(x, 0.f));
        }
    }
    __syncthreads();

    // ---- GEMM2: [32,512] @ [512,128] ----
    wmma::fragment<wmma::accumulator, 16, 16, 8, float> c2[2];
    wmma::fill_fragment(c2[0], 0.0f);
    wmma::fill_fragment(c2[1], 0.0f);

    const int n02 = wn * 32;
    for (int kt = 0; kt < 16; kt++) {
        float4 pre[4];
        if (kt < 15) {
            const float4* src = (const float4*)g_w2r + (kt + 1) * 1024;
            #pragma unroll
            for (int q = 0; q < 4; q++) pre[q] = src[tid + q * 256];
        }
        const float* cur = sA + (kt & 1) * (32 * AS);

        #pragma unroll
        for (int ks = 0; ks < 4; ks++) {
            wmma::fragment<wmma::matrix_a, 16, 16, 8, wmma::precision::tf32, wmma::row_major> a2;
            wmma::load_matrix_sync(a2, sH + row0 * HS + kt * 32 + ks * 8, HS);
            #pragma unroll
            for (int j = 0; j < 2; j++) {
                wmma::fragment<wmma::matrix_b, 16, 16, 8, wmma::precision::tf32, wmma::row_major> b;
                wmma::load_matrix_sync(b, cur + (ks * 8) * AS + n02 + j * 16, AS);
                wmma::mma_sync(c2[j], a2, b, c2[j]);
            }
        }

        if (kt < 15) {
            float* nxt = sA + ((kt + 1) & 1) * (32 * AS);
            #pragma unroll
            for (int q = 0; q < 4; q++) {
                int i = tid + q * 256;
                int r = i >> 5, c4 = i & 31;
                ((float4*)(nxt + r * AS))[c4] = pre[q];
            }
        }
        __syncthreads();
    }

    // ---- epilogue: stage C2 to sA (32x128), +b2, *ns, store y ----
    #pragma unroll
    for (int j = 0; j < 2; j++)
        wmma::store_matrix_sync(sA + row0 * 128 + n02 + j * 16, c2[j], 128, wmma::mem_row_major);
    __syncthreads();

    for (int i = tid; i < 4096; i += 256) {
        int r = i >> 7, col = i & 127;
        int row = n0g + r;
        g_y[(size_t)row * 128 + col] = (sA[i] + __ldg(&b2[col])) * g_ns[row];
    }
}

// ------------------------------------------------------------------
// Conv transform on tf32 wmma (unchanged).
__global__ void __launch_bounds__(256) conv_kernel(
    const float* __restrict__ bc, float* __restrict__ out_ext,
    int which, int to_y)
{
    __shared__ float sA[32 * AS];
    __shared__ float sW[2][16 * AS];

    const float* Wcr = which ? g_wc1r : g_wc0r;
    const int tid = threadIdx.x;
    const int w   = tid >> 5;
    const int wm  = w & 1;
    const int wn  = w >> 1;
    const int n0  = blockIdx.x * 32;

    #pragma unroll
    for (int q = 0; q < 4; q++) {
        int i = tid + q * 256;
        int r = i >> 5, c4 = i & 31;
        float4 v = ((const float4*)g_agg)[(size_t)(n0 + r) * 32 + c4];
        float ndv = g_nd[n0 + r];
        v.x = tf32r(v.x * ndv); v.y = tf32r(v.y * ndv);
        v.z = tf32r(v.z * ndv); v.w = tf32r(v.w * ndv);
        ((float4*)(sA + r * AS))[c4] = v;
    }
    {
        const float4* src = (const float4*)Wcr;
        #pragma unroll
        for (int q = 0; q < 2; q++) {
            int i = tid + q * 256;
            int r = i >> 5, c4 = i & 31;
            ((float4*)(sW[0] + r * AS))[c4] = src[i];
        }
    }
    __syncthreads();

    wmma::fragment<wmma::accumulator, 16, 16, 8, float> c[2];
    wmma::fill_fragment(c[0], 0.0f);
    wmma::fill_fragment(c[1], 0.0f);

    for (int kt = 0; kt < 8; kt++) {
        float4 pre[2];
        if (kt < 7) {
            const float4* src = (const float4*)Wcr + (kt + 1) * 512;
            #pragma unroll
            for (int q = 0; q < 2; q++) pre[q] = src[tid + q * 256];
        }
        const float* cur = sW[kt & 1];

        #pragma unroll
        for (int ks = 0; ks < 2; ks++) {
            wmma::fragment<wmma::matrix_a, 16, 16, 8, wmma::precision::tf32, wmma::row_major> a;
            wmma::load_matrix_sync(a, sA + (wm * 16) * AS + kt * 16 + ks * 8, AS);
            #pragma unroll
            for (int j = 0; j < 2; j++) {
                wmma::fragment<wmma::matrix_b, 16, 16, 8, wmma::precision::tf32, wmma::row_major> b;
                wmma::load_matrix_sync(b, cur + (ks * 8) * AS + wn * 32 + j * 16, AS);
                wmma::mma_sync(c[j], a, b, c[j]);
            }
        }

        if (kt < 7) {
            float* nxt = sW[(kt + 1) & 1];
            #pragma unroll
            for (int q = 0; q < 2; q++) {
                int i = tid + q * 256;
                int r = i >> 5, c4 = i & 31;
                ((float4*)(nxt + r * AS))[c4] = pre[q];
            }
        }
        __syncthreads();
    }

    #pragma unroll
    for (int j = 0; j < 2; j++)
        wmma::store_matrix_sync(sA + (wm * 16) * 128 + wn * 32 + j * 16,
                                c[j], 128, wmma::mem_row_major);
    __syncthreads();

    for (int i = tid; i < 4096; i += 256) {
        int r = i >> 7, col = i & 127;
        int row = n0 + r;
        float z = fmaxf(sA[i] + __ldg(&bc[col]), 0.f);
        if (to_y) g_y[(size_t)row * 128 + col] = z * g_ns[row];
        else      out_ext[(size_t)row * 128 + col] = z;
    }
}

// ------------------------------------------------------------------
extern "C" void kernel_launch(void* const* d_in, const int* in_sizes, int n_in,
                              void* d_out, int out_size)
{
    const float* feat   = (const float*)d_in[0];
    const int*   labels = (const int*)  d_in[1];
    const int*   esrc   = (const int*)  d_in[2];
    const int*   edst   = (const int*)  d_in[3];
    const float* emb    = (const float*)d_in[4];
    const float* W1     = (const float*)d_in[5];
    const float* b1     = (const float*)d_in[6];
    const float* g1     = (const float*)d_in[7];
    const float* be1    = (const float*)d_in[8];
    const float* W2     = (const float*)d_in[9];
    const float* b2     = (const float*)d_in[10];
    const float* Wc0    = (const float*)d_in[11];
    const float* bc0    = (const float*)d_in[12];
    const float* Wc1    = (const float*)d_in[13];
    const float* bc1    = (const float*)d_in[14];
    float* out = (float*)d_out;

    cudaFuncSetAttribute(mlp_kernel, cudaFuncAttributeMaxDynamicSharedMemorySize,
                         MLP_SMEM_BYTES);

    // launch order keeps mlp 4th (ncu capture window)
    zero_deg_kernel<<<(NN + 255) / 256, 256>>>();
    deg_round_kernel<<<(EE + 255) / 256, 256>>>(esrc, edst, W1, W2, Wc0, Wc1);
    norm_prep_kernel<<<(NN + 255) / 256, 256>>>(emb, W1, b1);
    mlp_kernel<<<NN / 32, 256, MLP_SMEM_BYTES>>>(feat, labels, g1, be1, b2);

    fill_kernel<<<(EE + 255) / 256, 256>>>(esrc, edst);

    // layer 1
    gather_kernel<<<(NN * 32 + 255) / 256, 256>>>();
    conv_kernel<<<NN / 32, 256>>>(bc0, nullptr, 0, 1);

    // layer 2
    gather_kernel<<<(NN * 32 + 255) / 256, 256>>>();
    conv_kernel<<<NN / 32, 256>>>(bc1, out, 1, 0);
}